// round 11
// baseline (speedup 1.0000x reference)
#include <cuda_runtime.h>
#include <math.h>
#include <float.h>

// Problem constants (fixed shapes from setup_inputs)
#define BQ   4
#define HTOT 32
#define HKV  8
#define GQ   4
#define DD   128
#define PP   128
#define SS   64
#define KP   16
#define NGROUP (BQ*HKV*GQ)   // 128
#define NEGV (-1000000000.0f)

// Scratch (no allocations allowed)
__device__ float g_qh[BQ*HKV*GQ*DD];
__device__ float g_curscore[NGROUP];
__device__ float g_scores[NGROUP*PP*SS];      // 4 MB
__device__ float g_pagestats[NGROUP*PP];
__device__ int   g_sel[NGROUP*KP];
__device__ float g_m[NGROUP];
__device__ float g_invl[NGROUP];

__device__ __forceinline__ float sm_scale_f32() {
    return (float)0.08838834764831845;   // f32(1/sqrt(128))
}

// ---------------------------------------------------------------------------
// Kernel 0: RoPE(q), RoPE(k_cur), cur_score = qh . k_cur * sm_scale
// CORRECTNESS-CRITICAL arithmetic (validated R9): libdevice powf/cosf/sinf,
// f32 division, unfused mul/sub. Do not change.
// ---------------------------------------------------------------------------
__global__ void rope_kernel(const float* __restrict__ q,
                            const float* __restrict__ k,
                            const int*   __restrict__ timestep)
{
    int bh = blockIdx.x;            // b*8 + h
    int b  = bh >> 3;
    int h  = bh & 7;
    int d  = threadIdx.x;

    int ts = timestep ? timestep[0] : 8192;
    float pos = (float)(ts - 1);

    int i = d & 63;
    float x    = (float)i * 0.015625f;       // exact
    float pf   = powf(10000.0f, x);          // libdevice __nv_powf (precise)
    float invf = __fdiv_rn(1.0f, pf);        // f32 IEEE division
    float ang  = __fmul_rn(pos, invf);
    float c  = cosf(ang);                    // libdevice __nv_cosf
    float sn = sinf(ang);                    // libdevice __nv_sinf

    const float* kb = k + bh * DD;
    float kx1 = kb[i], kx2 = kb[i + 64];
    float kval = (d < 64)
        ? __fsub_rn(__fmul_rn(kx1, c),  __fmul_rn(kx2, sn))
        : __fadd_rn(__fmul_rn(kx1, sn), __fmul_rn(kx2, c));

    __shared__ float red[128];
    for (int g = 0; g < GQ; g++) {
        const float* qb = q + ((b * HTOT) + h * GQ + g) * DD;
        float qx1 = qb[i], qx2 = qb[i + 64];
        float qval = (d < 64)
            ? __fsub_rn(__fmul_rn(qx1, c),  __fmul_rn(qx2, sn))
            : __fadd_rn(__fmul_rn(qx1, sn), __fmul_rn(qx2, c));
        g_qh[(bh * GQ + g) * DD + d] = qval;

        red[d] = qval * kval;
        __syncthreads();
        for (int off = 64; off; off >>= 1) {
            if (d < off) red[d] += red[d + off];
            __syncthreads();
        }
        if (d == 0) g_curscore[bh * GQ + g] = red[0] * sm_scale_f32();
        __syncthreads();
    }
}

// ---------------------------------------------------------------------------
// Kernel 1: full scores + per-page max — direct-gmem, register-resident.
// R1-validated structure (accumulation order proven irrelevant to ranking):
//   kc[d] = f32(k_int)*sk (rounded per element), fma into 4 lane-partials,
//   butterfly sum across 32 lanes, separate *sm_scale.
// grid (P=128, HKV=8, B=4), 256 threads = 8 warps; warp w -> tokens w*8..w*8+7
// ---------------------------------------------------------------------------
__global__ __launch_bounds__(256)
void score_kernel(const int*   __restrict__ k_cache,
                  const float* __restrict__ kvscale,
                  const int*   __restrict__ lengths)
{
    int p = blockIdx.x;
    int h = blockIdx.y;
    int b = blockIdx.z;
    int tid  = threadIdx.x;
    int w    = tid >> 5;
    int lane = tid & 31;
    int bh   = b * HKV + h;
    int gbase = bh * GQ;

    int len = lengths[b];
    if (len < 1) len = 1;

    if (p * SS >= len) {
        // fully masked page: fill scores with NEG, page stats NEG (no K load)
        int g = tid >> 6, s = tid & 63;   // 256 threads = 4*64 exactly
        g_scores[(((size_t)(gbase + g)) * PP + p) * SS + s] = NEGV;
        if (tid < GQ) g_pagestats[(gbase + tid) * PP + p] = NEGV;
        return;
    }

    float sk = kvscale[0];

    // q fragment: qreg[g][j] = qh[g][lane*4+j]
    float qreg[GQ][4];
    #pragma unroll
    for (int g = 0; g < GQ; g++) {
        float4 qv = *(const float4*)&g_qh[(gbase + g) * DD + lane * 4];
        qreg[g][0] = qv.x; qreg[g][1] = qv.y; qreg[g][2] = qv.z; qreg[g][3] = qv.w;
    }

    const int* kbase = k_cache + (((size_t)(b * PP + p)) * SS) * (HKV * DD) + h * DD;

    float gmax = -FLT_MAX;   // lanes 0..3 track max for their g
    #pragma unroll
    for (int iTok = 0; iTok < 8; iTok++) {
        int s = w * 8 + iTok;
        int4 kv = *(const int4*)(kbase + (size_t)s * (HKV * DD) + lane * 4);
        // kc = f32(int)*sk, rounded per element (matches R9-validated path)
        float k0 = __fmul_rn((float)kv.x, sk);
        float k1 = __fmul_rn((float)kv.y, sk);
        float k2 = __fmul_rn((float)kv.z, sk);
        float k3 = __fmul_rn((float)kv.w, sk);

        float part0 = k0*qreg[0][0]; part0 = fmaf(k1, qreg[0][1], part0);
        part0 = fmaf(k2, qreg[0][2], part0); part0 = fmaf(k3, qreg[0][3], part0);
        float part1 = k0*qreg[1][0]; part1 = fmaf(k1, qreg[1][1], part1);
        part1 = fmaf(k2, qreg[1][2], part1); part1 = fmaf(k3, qreg[1][3], part1);
        float part2 = k0*qreg[2][0]; part2 = fmaf(k1, qreg[2][1], part2);
        part2 = fmaf(k2, qreg[2][2], part2); part2 = fmaf(k3, qreg[2][3], part2);
        float part3 = k0*qreg[3][0]; part3 = fmaf(k1, qreg[3][1], part3);
        part3 = fmaf(k2, qreg[3][2], part3); part3 = fmaf(k3, qreg[3][3], part3);

        #pragma unroll
        for (int off = 16; off; off >>= 1) {
            part0 += __shfl_xor_sync(0xffffffffu, part0, off);
            part1 += __shfl_xor_sync(0xffffffffu, part1, off);
            part2 += __shfl_xor_sync(0xffffffffu, part2, off);
            part3 += __shfl_xor_sync(0xffffffffu, part3, off);
        }

        if (lane < 4) {
            float dot = (lane == 0) ? part0 : (lane == 1) ? part1 :
                        (lane == 2) ? part2 : part3;
            int pos = p * SS + s;
            float sc = (pos < len) ? __fmul_rn(dot, sm_scale_f32()) : NEGV;
            g_scores[(((size_t)(gbase + lane)) * PP + p) * SS + s] = sc;
            gmax = fmaxf(gmax, sc);
        }
    }

    __shared__ float smax[8][4];
    if (lane < 4) smax[w][lane] = gmax;
    __syncthreads();
    if (tid < 4) {
        float m = smax[0][tid];
        #pragma unroll
        for (int ww = 1; ww < 8; ww++) m = fmaxf(m, smax[ww][tid]);
        g_pagestats[(gbase + tid) * PP + p] = m;
    }
}

// ---------------------------------------------------------------------------
// Kernel 2 (fused): top-k (warp 0) + softmax stats + out init.
// grid 128 blocks (group), 256 threads.
// ---------------------------------------------------------------------------
__global__ __launch_bounds__(256)
void topk_softmax_kernel(const float* __restrict__ v,
                         float*       __restrict__ out,
                         float*       __restrict__ out_idx)
{
    int grp = blockIdx.x;
    int b = grp >> 5;
    int h = (grp >> 2) & 7;
    int g = grp & 3;
    int tid  = threadIdx.x;
    int lane = tid & 31;
    int w    = tid >> 5;

    __shared__ int   selS[KP];
    __shared__ float ssc[KP * SS];
    __shared__ float wredm[8];
    __shared__ float wreds[8];
    __shared__ float bcast[2];

    // ---- top-k on warp 0 (lax.top_k semantics: desc value, smaller idx first)
    if (w == 0) {
        float vals[4];
        #pragma unroll
        for (int j = 0; j < 4; j++) {
            int idx = j * 32 + lane;
            vals[j] = (idx < PP - 1) ? g_pagestats[grp * PP + idx] : -FLT_MAX;
        }
        for (int kk = 0; kk < KP - 1; kk++) {
            float bv = -FLT_MAX; int bi = 0x7fffffff;
            #pragma unroll
            for (int j = 0; j < 4; j++) {
                int idx = j * 32 + lane;
                if (vals[j] > bv || (vals[j] == bv && idx < bi)) { bv = vals[j]; bi = idx; }
            }
            #pragma unroll
            for (int off = 16; off; off >>= 1) {
                float ov = __shfl_xor_sync(0xffffffffu, bv, off);
                int   oi = __shfl_xor_sync(0xffffffffu, bi, off);
                if (ov > bv || (ov == bv && oi < bi)) { bv = ov; bi = oi; }
            }
            if (lane == 0) {
                selS[kk] = bi;
                g_sel[grp * KP + kk]   = bi;
                out_idx[grp * KP + kk] = (float)bi;
            }
            int slot = bi >> 5, ol = bi & 31;
            if (lane == ol) {
                if (slot == 0) vals[0] = -FLT_MAX;
                else if (slot == 1) vals[1] = -FLT_MAX;
                else if (slot == 2) vals[2] = -FLT_MAX;
                else vals[3] = -FLT_MAX;
            }
        }
        if (lane == 0) {
            selS[KP - 1] = PP - 1;
            g_sel[grp * KP + KP - 1]   = PP - 1;
            out_idx[grp * KP + KP - 1] = (float)(PP - 1);
        }
    }
    __syncthreads();

    // ---- gather selected scores
    #pragma unroll
    for (int it = 0; it < 4; it++) {
        int t = it * 256 + tid;             // 0..1023
        int kk = t >> 6, s = t & 63;
        ssc[t] = g_scores[(((size_t)grp) * PP + selS[kk]) * SS + s];
    }
    __syncthreads();

    float cur = g_curscore[grp];

    // ---- max (warp shuffles, 2 levels)
    float m = (tid == 0) ? cur : -FLT_MAX;
    #pragma unroll
    for (int it = 0; it < 4; it++) m = fmaxf(m, ssc[it * 256 + tid]);
    #pragma unroll
    for (int off = 16; off; off >>= 1)
        m = fmaxf(m, __shfl_xor_sync(0xffffffffu, m, off));
    if (lane == 0) wredm[w] = m;
    __syncthreads();
    if (tid < 32) {
        float x = (lane < 8) ? wredm[lane] : -FLT_MAX;
        #pragma unroll
        for (int off = 4; off; off >>= 1)
            x = fmaxf(x, __shfl_xor_sync(0xffffffffu, x, off));
        if (lane == 0) bcast[0] = x;
    }
    __syncthreads();
    m = bcast[0];

    // ---- sum (warp shuffles, 2 levels)
    float sum = (tid == 0) ? expf(cur - m) : 0.0f;
    #pragma unroll
    for (int it = 0; it < 4; it++) sum += expf(ssc[it * 256 + tid] - m);
    #pragma unroll
    for (int off = 16; off; off >>= 1)
        sum += __shfl_xor_sync(0xffffffffu, sum, off);
    if (lane == 0) wreds[w] = sum;
    __syncthreads();
    if (tid < 32) {
        float x = (lane < 8) ? wreds[lane] : 0.0f;
        #pragma unroll
        for (int off = 4; off; off >>= 1)
            x += __shfl_xor_sync(0xffffffffu, x, off);
        if (lane == 0) bcast[1] = x;
    }
    __syncthreads();
    float invl = 1.0f / bcast[1];

    if (tid == 0) { g_m[grp] = m; g_invl[grp] = invl; }

    if (tid < DD) {
        float pcur = expf(cur - m) * invl;
        out[((b * HTOT) + h * GQ + g) * DD + tid] =
            pcur * v[(b * HKV + h) * DD + tid];
    }
}

// ---------------------------------------------------------------------------
// Kernel 3: weighted V accumulation, one block per (group, selected page).
// grid 2048 blocks, 256 threads = 8 warps; warp w -> tokens w*8..w*8+7,
// lane -> d-quad (int4 = 16B loads). Cross-warp reduce in smem, one
// atomicAdd per d.
// ---------------------------------------------------------------------------
__global__ __launch_bounds__(256)
void av_kernel(const int*   __restrict__ v_cache,
               const float* __restrict__ kvscale,
               float*       __restrict__ out)
{
    int blk = blockIdx.x;
    int grp = blk >> 4;
    int kk  = blk & 15;
    int b = grp >> 5;
    int h = (grp >> 2) & 7;
    int g = grp & 3;
    int tid  = threadIdx.x;
    int w    = tid >> 5;
    int lane = tid & 31;

    __shared__ float e[SS];
    __shared__ float4 part4[8][32];   // 4 KB
    __shared__ int anyflag;

    int page  = g_sel[grp * KP + kk];
    float m    = g_m[grp];
    float invl = g_invl[grp];

    if (tid == 0) anyflag = 0;
    __syncthreads();
    if (tid < SS) {
        float ev = expf(g_scores[(((size_t)grp) * PP + page) * SS + tid] - m) * invl;
        e[tid] = ev;
        if (ev > 0.0f) anyflag = 1;
    }
    __syncthreads();
    if (!anyflag) return;   // fully masked page (only possible for page 127)

    const int* vb = v_cache
        + (((size_t)(b * PP + page)) * SS + w * 8) * (HKV * DD)
        + h * DD + lane * 4;

    float4 acc = make_float4(0.f, 0.f, 0.f, 0.f);
    #pragma unroll
    for (int s = 0; s < 8; s++) {
        int4 vv = *(const int4*)(vb + (size_t)s * (HKV * DD));
        float we = e[w * 8 + s];
        acc.x = fmaf(we, (float)vv.x, acc.x);
        acc.y = fmaf(we, (float)vv.y, acc.y);
        acc.z = fmaf(we, (float)vv.z, acc.z);
        acc.w = fmaf(we, (float)vv.w, acc.w);
    }
    part4[w][lane] = acc;
    __syncthreads();

    if (tid < DD) {
        const float* pf = (const float*)part4;   // [8][128]
        float sum = pf[tid];
        #pragma unroll
        for (int ww = 1; ww < 8; ww++) sum += pf[ww * DD + tid];
        atomicAdd(&out[((b * HTOT) + h * GQ + g) * DD + tid],
                  sum * kvscale[1]);
    }
}

// ---------------------------------------------------------------------------
extern "C" void kernel_launch(void* const* d_in, const int* in_sizes, int n_in,
                              void* d_out, int out_size)
{
    const float* q        = (const float*)d_in[0];
    const float* k        = (const float*)d_in[1];
    const float* v        = (const float*)d_in[2];
    const float* kvscale  = (const float*)d_in[3];
    const int*   k_cache  = (const int*)  d_in[4];
    const int*   v_cache  = (const int*)  d_in[5];
    const int*   lengths  = (const int*)  d_in[6];
    const int*   timestep = (n_in >= 8) ? (const int*)d_in[7] : nullptr;

    float* out = (float*)d_out;                 // [B,H,D] = 16384 floats
    float* out_idx = out + BQ * HTOT * DD;      // [B,H,KP] = 2048 (as float)

    rope_kernel<<<BQ * HKV, 128>>>(q, k, timestep);
    score_kernel<<<dim3(PP, HKV, BQ), 256>>>(k_cache, kvscale, lengths);
    topk_softmax_kernel<<<NGROUP, 256>>>(v, out, out_idx);
    av_kernel<<<NGROUP * KP, 256>>>(v_cache, kvscale, out);

    (void)in_sizes; (void)out_size;
}

// round 12
// speedup vs baseline: 1.0278x; 1.0278x over previous
#include <cuda_runtime.h>
#include <math.h>
#include <float.h>

// Problem constants (fixed shapes from setup_inputs)
#define BQ   4
#define HTOT 32
#define HKV  8
#define GQ   4
#define DD   128
#define PP   128
#define SS   64
#define KP   16
#define NGROUP (BQ*HKV*GQ)   // 128
#define NEGV (-1000000000.0f)

// Scratch (no allocations allowed)
__device__ float g_qh[BQ*HKV*GQ*DD];
__device__ float g_curscore[NGROUP];
__device__ float g_scores[NGROUP*PP*SS];      // 4 MB
__device__ float g_pagestats[NGROUP*PP];
__device__ int   g_sel[NGROUP*KP];
__device__ float g_m[NGROUP];
__device__ float g_invl[NGROUP];

__device__ __forceinline__ float sm_scale_f32() {
    return (float)0.08838834764831845;   // f32(1/sqrt(128))
}

// Blackwell packed f32x2 FMA (2 IEEE f32 FMAs per instruction, fma pipe)
__device__ __forceinline__ unsigned long long ffma2(
    unsigned long long a, unsigned long long b, unsigned long long c)
{
    unsigned long long d;
    asm("fma.rn.f32x2 %0, %1, %2, %3;" : "=l"(d) : "l"(a), "l"(b), "l"(c));
    return d;
}

// ---------------------------------------------------------------------------
// Kernel 0: RoPE(q), RoPE(k_cur), cur_score = qh . k_cur * sm_scale
// CORRECTNESS-CRITICAL arithmetic (validated R9): libdevice powf/cosf/sinf,
// f32 division, unfused mul/sub. Do not change.
// ---------------------------------------------------------------------------
__global__ void rope_kernel(const float* __restrict__ q,
                            const float* __restrict__ k,
                            const int*   __restrict__ timestep)
{
    int bh = blockIdx.x;            // b*8 + h
    int b  = bh >> 3;
    int h  = bh & 7;
    int d  = threadIdx.x;

    int ts = timestep ? timestep[0] : 8192;
    float pos = (float)(ts - 1);

    int i = d & 63;
    float x    = (float)i * 0.015625f;       // exact
    float pf   = powf(10000.0f, x);          // libdevice __nv_powf (precise)
    float invf = __fdiv_rn(1.0f, pf);        // f32 IEEE division
    float ang  = __fmul_rn(pos, invf);
    float c  = cosf(ang);                    // libdevice __nv_cosf
    float sn = sinf(ang);                    // libdevice __nv_sinf

    const float* kb = k + bh * DD;
    float kx1 = kb[i], kx2 = kb[i + 64];
    float kval = (d < 64)
        ? __fsub_rn(__fmul_rn(kx1, c),  __fmul_rn(kx2, sn))
        : __fadd_rn(__fmul_rn(kx1, sn), __fmul_rn(kx2, c));

    __shared__ float red[128];
    for (int g = 0; g < GQ; g++) {
        const float* qb = q + ((b * HTOT) + h * GQ + g) * DD;
        float qx1 = qb[i], qx2 = qb[i + 64];
        float qval = (d < 64)
            ? __fsub_rn(__fmul_rn(qx1, c),  __fmul_rn(qx2, sn))
            : __fadd_rn(__fmul_rn(qx1, sn), __fmul_rn(qx2, c));
        g_qh[(bh * GQ + g) * DD + d] = qval;

        red[d] = qval * kval;
        __syncthreads();
        for (int off = 64; off; off >>= 1) {
            if (d < off) red[d] += red[d + off];
            __syncthreads();
        }
        if (d == 0) g_curscore[bh * GQ + g] = red[0] * sm_scale_f32();
        __syncthreads();
    }
}

// ---------------------------------------------------------------------------
// Kernel 1: full scores + per-page max.
// Scale (sk*sm) folded into q (R1-validated noise class — selection proven
// insensitive to this vs per-element rounding). K staged in smem as raw f32,
// compute via packed FFMA2 (fma.rn.f32x2), 2 independent accumulators.
// grid (P=128, HKV=8, B=4), 256 threads: thread -> (s = tid>>2, g = tid&3)
// ---------------------------------------------------------------------------
#define KROW 132   // padded row stride in floats (132*4=528B, 16B aligned)

__global__ __launch_bounds__(256)
void score_kernel(const int*   __restrict__ k_cache,
                  const float* __restrict__ kvscale,
                  const int*   __restrict__ lengths)
{
    int p = blockIdx.x;
    int h = blockIdx.y;
    int b = blockIdx.z;
    int tid  = threadIdx.x;
    int bh   = b * HKV + h;
    int gbase = bh * GQ;

    int len = lengths[b];
    if (len < 1) len = 1;

    if (p * SS >= len) {
        // fully masked page: fill scores with NEG, page stats NEG (no K load)
        int g = tid >> 6, s = tid & 63;   // 256 threads = 4*64 exactly
        g_scores[(((size_t)(gbase + g)) * PP + p) * SS + s] = NEGV;
        if (tid < GQ) g_pagestats[(gbase + tid) * PP + p] = NEGV;
        return;
    }

    __shared__ float kS[SS * KROW];   // raw f32(int), unscaled
    __shared__ float qS[GQ * KROW];   // q * (sk*sm_scale)
    __shared__ float smax[8][4];

    float ss = __fmul_rn(kvscale[0], sm_scale_f32());

    // Stage K tile: 64 tokens x 128 ints -> f32 (I2F once per element).
    {
        const int4* kbase = (const int4*)(k_cache
            + (((size_t)(b * PP + p)) * SS) * (HKV * DD) + h * DD);
        #pragma unroll
        for (int it = 0; it < 8; it++) {
            int idx = it * 256 + tid;       // 0..2047
            int s = idx >> 5;               // token
            int j = idx & 31;               // int4 within row
            int4 kv = kbase[(size_t)s * (HKV * DD / 4) + j];
            float* dst = &kS[s * KROW + j * 4];
            dst[0] = (float)kv.x;
            dst[1] = (float)kv.y;
            dst[2] = (float)kv.z;
            dst[3] = (float)kv.w;
        }
        #pragma unroll
        for (int it = 0; it < 2; it++) {
            int idx = it * 256 + tid;       // 0..511
            int g = idx >> 7, d2 = idx & 127;
            qS[g * KROW + d2] = __fmul_rn(g_qh[(gbase + g) * DD + d2], ss);
        }
    }
    __syncthreads();

    int s = tid >> 2;     // token 0..63
    int g = tid & 3;      // group 0..3

    // Packed dual-FMA dot product, two independent f32x2 accumulators.
    const ulonglong2* kq = (const ulonglong2*)&kS[s * KROW];
    const ulonglong2* qq = (const ulonglong2*)&qS[g * KROW];
    unsigned long long acc0 = 0ull, acc1 = 0ull;   // (0.0f,0.0f) packed
    #pragma unroll
    for (int j = 0; j < 32; j++) {
        ulonglong2 kv = kq[j];
        ulonglong2 qv = qq[j];
        acc0 = ffma2(qv.x, kv.x, acc0);
        acc1 = ffma2(qv.y, kv.y, acc1);
    }
    float a0x, a0y, a1x, a1y;
    asm("mov.b64 {%0,%1}, %2;" : "=f"(a0x), "=f"(a0y) : "l"(acc0));
    asm("mov.b64 {%0,%1}, %2;" : "=f"(a1x), "=f"(a1y) : "l"(acc1));
    float dot = (a0x + a0y) + (a1x + a1y);

    int pos = p * SS + s;
    float sc = (pos < len) ? dot : NEGV;
    g_scores[(((size_t)(gbase + g)) * PP + p) * SS + s] = sc;

    // per-(page,g) max: reduce over tokens (lanes with same g, stride 4)
    float gm = sc;
    #pragma unroll
    for (int off = 4; off < 32; off <<= 1)
        gm = fmaxf(gm, __shfl_xor_sync(0xffffffffu, gm, off));
    int w = tid >> 5, lane = tid & 31;
    if (lane < 4) smax[w][lane] = gm;
    __syncthreads();
    if (tid < 4) {
        float m = smax[0][tid];
        #pragma unroll
        for (int ww = 1; ww < 8; ww++) m = fmaxf(m, smax[ww][tid]);
        g_pagestats[(gbase + tid) * PP + p] = m;
    }
}

// ---------------------------------------------------------------------------
// Kernel 2 (fused): top-k (warp 0) + softmax stats + out init.
// grid 128 blocks (group), 256 threads.
// ---------------------------------------------------------------------------
__global__ __launch_bounds__(256)
void topk_softmax_kernel(const float* __restrict__ v,
                         float*       __restrict__ out,
                         float*       __restrict__ out_idx)
{
    int grp = blockIdx.x;
    int b = grp >> 5;
    int h = (grp >> 2) & 7;
    int g = grp & 3;
    int tid  = threadIdx.x;
    int lane = tid & 31;
    int w    = tid >> 5;

    __shared__ int   selS[KP];
    __shared__ float ssc[KP * SS];
    __shared__ float wredm[8];
    __shared__ float wreds[8];
    __shared__ float bcast[2];

    // ---- top-k on warp 0 (lax.top_k semantics: desc value, smaller idx first)
    if (w == 0) {
        float vals[4];
        #pragma unroll
        for (int j = 0; j < 4; j++) {
            int idx = j * 32 + lane;
            vals[j] = (idx < PP - 1) ? g_pagestats[grp * PP + idx] : -FLT_MAX;
        }
        for (int kk = 0; kk < KP - 1; kk++) {
            float bv = -FLT_MAX; int bi = 0x7fffffff;
            #pragma unroll
            for (int j = 0; j < 4; j++) {
                int idx = j * 32 + lane;
                if (vals[j] > bv || (vals[j] == bv && idx < bi)) { bv = vals[j]; bi = idx; }
            }
            #pragma unroll
            for (int off = 16; off; off >>= 1) {
                float ov = __shfl_xor_sync(0xffffffffu, bv, off);
                int   oi = __shfl_xor_sync(0xffffffffu, bi, off);
                if (ov > bv || (ov == bv && oi < bi)) { bv = ov; bi = oi; }
            }
            if (lane == 0) {
                selS[kk] = bi;
                g_sel[grp * KP + kk]   = bi;
                out_idx[grp * KP + kk] = (float)bi;
            }
            int slot = bi >> 5, ol = bi & 31;
            if (lane == ol) {
                if (slot == 0) vals[0] = -FLT_MAX;
                else if (slot == 1) vals[1] = -FLT_MAX;
                else if (slot == 2) vals[2] = -FLT_MAX;
                else vals[3] = -FLT_MAX;
            }
        }
        if (lane == 0) {
            selS[KP - 1] = PP - 1;
            g_sel[grp * KP + KP - 1]   = PP - 1;
            out_idx[grp * KP + KP - 1] = (float)(PP - 1);
        }
    }
    __syncthreads();

    // ---- gather selected scores
    #pragma unroll
    for (int it = 0; it < 4; it++) {
        int t = it * 256 + tid;             // 0..1023
        int kk = t >> 6, s = t & 63;
        ssc[t] = g_scores[(((size_t)grp) * PP + selS[kk]) * SS + s];
    }
    __syncthreads();

    float cur = g_curscore[grp];

    // ---- max (warp shuffles, 2 levels)
    float m = (tid == 0) ? cur : -FLT_MAX;
    #pragma unroll
    for (int it = 0; it < 4; it++) m = fmaxf(m, ssc[it * 256 + tid]);
    #pragma unroll
    for (int off = 16; off; off >>= 1)
        m = fmaxf(m, __shfl_xor_sync(0xffffffffu, m, off));
    if (lane == 0) wredm[w] = m;
    __syncthreads();
    if (tid < 32) {
        float x = (lane < 8) ? wredm[lane] : -FLT_MAX;
        #pragma unroll
        for (int off = 4; off; off >>= 1)
            x = fmaxf(x, __shfl_xor_sync(0xffffffffu, x, off));
        if (lane == 0) bcast[0] = x;
    }
    __syncthreads();
    m = bcast[0];

    // ---- sum (warp shuffles, 2 levels)
    float sum = (tid == 0) ? expf(cur - m) : 0.0f;
    #pragma unroll
    for (int it = 0; it < 4; it++) sum += expf(ssc[it * 256 + tid] - m);
    #pragma unroll
    for (int off = 16; off; off >>= 1)
        sum += __shfl_xor_sync(0xffffffffu, sum, off);
    if (lane == 0) wreds[w] = sum;
    __syncthreads();
    if (tid < 32) {
        float x = (lane < 8) ? wreds[lane] : 0.0f;
        #pragma unroll
        for (int off = 4; off; off >>= 1)
            x += __shfl_xor_sync(0xffffffffu, x, off);
        if (lane == 0) bcast[1] = x;
    }
    __syncthreads();
    float invl = 1.0f / bcast[1];

    if (tid == 0) { g_m[grp] = m; g_invl[grp] = invl; }

    if (tid < DD) {
        float pcur = expf(cur - m) * invl;
        out[((b * HTOT) + h * GQ + g) * DD + tid] =
            pcur * v[(b * HKV + h) * DD + tid];
    }
}

// ---------------------------------------------------------------------------
// Kernel 3: weighted V accumulation, one block per (group, selected page).
// grid 2048 blocks, 256 threads = 8 warps; warp w -> tokens w*8..w*8+7,
// lane -> d-quad. All 8 int4 loads front-batched into registers (MLP=8),
// then weighted accumulate; cross-warp reduce in smem; one atomicAdd per d.
// ---------------------------------------------------------------------------
__global__ __launch_bounds__(256)
void av_kernel(const int*   __restrict__ v_cache,
               const float* __restrict__ kvscale,
               float*       __restrict__ out)
{
    int blk = blockIdx.x;
    int grp = blk >> 4;
    int kk  = blk & 15;
    int b = grp >> 5;
    int h = (grp >> 2) & 7;
    int g = grp & 3;
    int tid  = threadIdx.x;
    int w    = tid >> 5;
    int lane = tid & 31;

    __shared__ float e[SS];
    __shared__ float4 part4[8][32];   // 4 KB
    __shared__ int anyflag;

    int page  = g_sel[grp * KP + kk];
    float m    = g_m[grp];
    float invl = g_invl[grp];

    if (tid == 0) anyflag = 0;
    __syncthreads();
    if (tid < SS) {
        float ev = expf(g_scores[(((size_t)grp) * PP + page) * SS + tid] - m) * invl;
        e[tid] = ev;
        if (ev > 0.0f) anyflag = 1;
    }
    __syncthreads();
    if (!anyflag) return;   // fully masked page (only possible for page 127)

    const int* vb = v_cache
        + (((size_t)(b * PP + page)) * SS + w * 8) * (HKV * DD)
        + h * DD + lane * 4;

    // Front-batch all 8 token loads (independent addresses -> MLP 8)
    int4 r[8];
    #pragma unroll
    for (int s = 0; s < 8; s++)
        r[s] = *(const int4*)(vb + (size_t)s * (HKV * DD));

    float4 acc = make_float4(0.f, 0.f, 0.f, 0.f);
    #pragma unroll
    for (int s = 0; s < 8; s++) {
        float we = e[w * 8 + s];
        acc.x = fmaf(we, (float)r[s].x, acc.x);
        acc.y = fmaf(we, (float)r[s].y, acc.y);
        acc.z = fmaf(we, (float)r[s].z, acc.z);
        acc.w = fmaf(we, (float)r[s].w, acc.w);
    }
    part4[w][lane] = acc;
    __syncthreads();

    if (tid < DD) {
        const float* pf = (const float*)part4;   // [8][128]
        float sum = pf[tid];
        #pragma unroll
        for (int ww = 1; ww < 8; ww++) sum += pf[ww * DD + tid];
        atomicAdd(&out[((b * HTOT) + h * GQ + g) * DD + tid],
                  sum * kvscale[1]);
    }
}

// ---------------------------------------------------------------------------
extern "C" void kernel_launch(void* const* d_in, const int* in_sizes, int n_in,
                              void* d_out, int out_size)
{
    const float* q        = (const float*)d_in[0];
    const float* k        = (const float*)d_in[1];
    const float* v        = (const float*)d_in[2];
    const float* kvscale  = (const float*)d_in[3];
    const int*   k_cache  = (const int*)  d_in[4];
    const int*   v_cache  = (const int*)  d_in[5];
    const int*   lengths  = (const int*)  d_in[6];
    const int*   timestep = (n_in >= 8) ? (const int*)d_in[7] : nullptr;

    float* out = (float*)d_out;                 // [B,H,D] = 16384 floats
    float* out_idx = out + BQ * HTOT * DD;      // [B,H,KP] = 2048 (as float)

    rope_kernel<<<BQ * HKV, 128>>>(q, k, timestep);
    score_kernel<<<dim3(PP, HKV, BQ), 256>>>(k_cache, kvscale, lengths);
    topk_softmax_kernel<<<NGROUP, 256>>>(v, out, out_idx);
    av_kernel<<<NGROUP * KP, 256>>>(v_cache, kvscale, out);

    (void)in_sizes; (void)out_size;
}